// round 16
// baseline (speedup 1.0000x reference)
#include <cuda_runtime.h>
#include <cuda_fp16.h>
#include <math.h>
#include <stdint.h>

// Problem dims
#define BD    128
#define SLEN  256
#define EDIM  512
#define HDIM  1024
#define ODIM  10
#define NG    4096
#define MTOT  (BD*SLEN)

#define NCTA  128
#define NTH   512     // 16 warps: 2 K-groups x 8 M-warps

// ---------------------------------------------------------------------------
// Device scratch
// ---------------------------------------------------------------------------
// gatesx layout: [s][hb(128)][g(4)][b(128)][8]
__device__ float g_gatesx[(long)SLEN * BD * NG];
__device__ float g_h[BD * HDIM];

__device__ __half g_h16[2][BD * HDIM];      // fp16 h, ping-pong
__device__ __half g_Whp[(long)NG * HDIM];   // fp16 W, n = cta*32 + g*8 + j
__device__ __half g_Wip[(long)NG * EDIM];   // fp16 W, n = g*1024 + col
__device__ __half g_e16[(long)MTOT * EDIM]; // fp16 gathered embeddings

// per-cohort dataflow flags: cohort c = producers of h cols [128c, 128c+128)
// monotonic counters (16 arrivals per cohort per step), zeroed in prep.
__device__ unsigned g_flag[8 * 32];

// ---------------------------------------------------------------------------
__device__ __forceinline__ void mma16816(float& d0, float& d1, float& d2, float& d3,
                                         uint32_t a0, uint32_t a1, uint32_t a2, uint32_t a3,
                                         uint32_t b0, uint32_t b1) {
    asm volatile("mma.sync.aligned.m16n8k16.row.col.f32.f16.f16.f32 "
                 "{%0,%1,%2,%3}, {%4,%5,%6,%7}, {%8,%9}, {%0,%1,%2,%3};"
                 : "+f"(d0), "+f"(d1), "+f"(d2), "+f"(d3)
                 : "r"(a0), "r"(a1), "r"(a2), "r"(a3), "r"(b0), "r"(b1));
}

__device__ __forceinline__ void ldsm4(uint32_t& r0, uint32_t& r1, uint32_t& r2,
                                      uint32_t& r3, uint32_t addr) {
    asm volatile("ldmatrix.sync.aligned.m8n8.x4.shared.b16 {%0,%1,%2,%3}, [%4];"
                 : "=r"(r0), "=r"(r1), "=r"(r2), "=r"(r3) : "r"(addr));
}

__device__ __forceinline__ void cpa16(uint32_t s, const void* g) {
    asm volatile("cp.async.cg.shared.global [%0], [%1], 16;\n" :: "r"(s), "l"(g));
}
#define CP_COMMIT() asm volatile("cp.async.commit_group;\n" ::: "memory")
template <int N> __device__ __forceinline__ void cp_wait() {
    asm volatile("cp.async.wait_group %0;\n" :: "n"(N) : "memory");
}
#define BARG(id) asm volatile("bar.sync %0, 256;" :: "r"(id) : "memory")

#define SWZ128(x) ((x) ^ (((x) >> 3) & 0x70))

// fast activations (__expf error ~1e-7 rel; negligible vs 3.5e-4 budget)
__device__ __forceinline__ float fsigmoid(float x) {
    return __fdividef(1.f, 1.f + __expf(-x));
}
__device__ __forceinline__ float ftanh(float x) {
    return 1.f - __fdividef(2.f, __expf(2.f * x) + 1.f);
}

// wait until cohort c's flag reaches target (lane0 acquire-poll + warp sync)
__device__ __forceinline__ void waitflag(int c, unsigned target) {
    if ((threadIdx.x & 31) == 0) {
        unsigned v;
        do {
            asm volatile("ld.acquire.gpu.u32 %0, [%1];"
                         : "=r"(v) : "l"(g_flag + c * 32) : "memory");
        } while (v < target);
    }
    __syncwarp();
}

// ---------------------------------------------------------------------------
// Merged prep (grid-stride): embedding gather+fp16, W packs, h/flag init.
// ---------------------------------------------------------------------------
__global__ void k_prep(const void* __restrict__ xv, const float* __restrict__ emb,
                       const float* __restrict__ Wii, const float* __restrict__ Wif,
                       const float* __restrict__ Wig, const float* __restrict__ Wio,
                       const float* __restrict__ Whi, const float* __restrict__ Whf,
                       const float* __restrict__ Whg, const float* __restrict__ Who) {
    const int nb = gridDim.x, blk = blockIdx.x, tid = threadIdx.x;

    __shared__ int s64;
    if (tid == 0) {
        const int* xw = (const int*)xv;
        int zeros = 0;
        for (int i = 0; i < 64; i++)
            if (xw[2 * i + 1] == 0) zeros++;
        s64 = (zeros >= 60) ? 1 : 0;
    }
    __syncthreads();

    // embeddings
    for (int m = blk; m < MTOT; m += nb) {
        long tok = s64 ? (long)((const long long*)xv)[m] : (long)((const int*)xv)[m];
        const float* src = emb + tok * EDIM;
        for (int k = tid; k < EDIM; k += 256)
            g_e16[(long)m * EDIM + k] = __float2half_rn(src[k]);
    }
    // input W: n = g*1024 + col
    for (int n = blk; n < NG; n += nb) {
        int g = n >> 10, col = n & 1023;
        const float* src = ((g == 0) ? Wii : (g == 1) ? Wif : (g == 2) ? Wig : Wio)
                           + (long)col * EDIM;
        for (int k = tid; k < EDIM; k += 256)
            g_Wip[(long)n * EDIM + k] = __float2half_rn(src[k]);
    }
    // recurrent W: n = hb*32 + g*8 + j
    for (int n = blk; n < NG; n += nb) {
        int hb = n >> 5, r = n & 31, g = r >> 3, j = r & 7;
        int h = hb * 8 + j;
        const float* src = ((g == 0) ? Whi : (g == 1) ? Whf : (g == 2) ? Whg : Who)
                           + (long)h * HDIM;
        for (int k = tid; k < HDIM; k += 256)
            g_Whp[(long)n * HDIM + k] = __float2half_rn(src[k]);
    }
    // init h and flags
    for (int i = blk * 256 + tid; i < BD * HDIM; i += nb * 256)
        g_h16[0][i] = __float2half(0.f);
    for (int i = blk * 256 + tid; i < 8 * 32; i += nb * 256)
        g_flag[i] = 0u;
}

// ---------------------------------------------------------------------------
// Input projection GEMM: [32768 x 512] @ [512 x 4096], fp16 single-term.
// ---------------------------------------------------------------------------
#define IP 24
__global__ __launch_bounds__(256)
void k_igemm_tc(const float* __restrict__ bi, const float* __restrict__ bf2,
                const float* __restrict__ bg, const float* __restrict__ bo) {
    __shared__ __align__(16) __half sm[2][2][128 * IP];

    const int tid = threadIdx.x;
    const int n0 = blockIdx.x * 128;
    const int M0 = blockIdx.y * 128;

    const int w = tid >> 5, lane = tid & 31;
    const int g = lane >> 2, tig = lane & 3;
    const int m0w = (w >> 1) * 32, n0w = (w & 1) * 64;

    const int sel0 = tid >> 7, idx0 = tid & 127;
    const __half* gp0 = sel0 ? (g_Wip + (long)(n0 + idx0) * EDIM)
                             : (g_e16 + (long)(M0 + idx0) * EDIM);

    float acc[2][8][4];
#pragma unroll
    for (int mt = 0; mt < 2; mt++)
#pragma unroll
        for (int nt = 0; nt < 8; nt++)
#pragma unroll
            for (int q = 0; q < 4; q++) acc[mt][nt][q] = 0.f;

    uint4 p0[2];
    p0[0] = ((const uint4*)gp0)[0]; p0[1] = ((const uint4*)gp0)[1];
    {
        uint4* d = (uint4*)(&sm[0][sel0][idx0 * IP]);
        d[0] = p0[0]; d[1] = p0[1];
    }
    __syncthreads();

    const int NSTAGE = EDIM / 16;
    for (int s = 0; s < NSTAGE; s++) {
        int buf = s & 1;
        bool more = (s + 1 < NSTAGE);
        if (more) {
            gp0 += 16;
            p0[0] = ((const uint4*)gp0)[0]; p0[1] = ((const uint4*)gp0)[1];
        }
        const __half* Am = sm[buf][0];
        const __half* Bm = sm[buf][1];
        const int kb = 2 * tig;

        uint32_t aF[2][4], bF[8][2];
#pragma unroll
        for (int mt = 0; mt < 2; mt++) {
            int rw = (m0w + mt * 16 + g) * IP + kb;
            aF[mt][0] = *(const uint32_t*)(Am + rw);
            aF[mt][1] = *(const uint32_t*)(Am + rw + 8 * IP);
            aF[mt][2] = *(const uint32_t*)(Am + rw + 8);
            aF[mt][3] = *(const uint32_t*)(Am + rw + 8 * IP + 8);
        }
#pragma unroll
        for (int nt = 0; nt < 8; nt++) {
            int cw = (n0w + nt * 8 + g) * IP + kb;
            bF[nt][0] = *(const uint32_t*)(Bm + cw);
            bF[nt][1] = *(const uint32_t*)(Bm + cw + 8);
        }
#pragma unroll
        for (int mt = 0; mt < 2; mt++)
#pragma unroll
            for (int nt = 0; nt < 8; nt++) {
                float* d = acc[mt][nt];
                mma16816(d[0], d[1], d[2], d[3], aF[mt][0], aF[mt][1], aF[mt][2], aF[mt][3], bF[nt][0], bF[nt][1]);
            }

        if (more) {
            uint4* d = (uint4*)(&sm[buf ^ 1][sel0][idx0 * IP]);
            d[0] = p0[0]; d[1] = p0[1];
        }
        __syncthreads();
    }

#pragma unroll
    for (int mt = 0; mt < 2; mt++) {
        int r0 = m0w + mt * 16 + g;
#pragma unroll
        for (int nt = 0; nt < 8; nt++) {
            int col  = n0w + nt * 8 + 2 * tig;
            int ncol = n0 + col;
            int gate = ncol >> 10, hcol = ncol & 1023;
            int hb = hcol >> 3, j = hcol & 7;
            const float* bptr = (gate == 0) ? bi : (gate == 1) ? bf2 : (gate == 2) ? bg : bo;
            float bv0 = bptr[hcol], bv1 = bptr[hcol + 1];
#pragma unroll
            for (int hf = 0; hf < 2; hf++) {
                int mrow = M0 + r0 + hf * 8;
                int b = mrow >> 8, ss = mrow & 255;
                float2 v = make_float2(acc[mt][nt][hf * 2] + bv0, acc[mt][nt][hf * 2 + 1] + bv1);
                long off = ((((long)ss * 128 + hb) * 4 + gate) * 128 + b) * 8 + j;
                *(float2*)(g_gatesx + off) = v;
            }
        }
    }
}

// ---------------------------------------------------------------------------
// Persistent LSTM step kernel v11: kc=64, 4-deep cp.async ring, ONE BARG per
// chunk, cohort flags + rotation (identical global k order to v10).
// ---------------------------------------------------------------------------
#define SM_A   0                       // 2 groups x 4 bufs x 16KB = 128KB
#define SM_W   131072                  // 64KB resident W
#define SM_R   (131072 + 65536)        // 16KB reduce
#define SMEM_TC11 (SM_R + 16384)       // 212992

__global__ __launch_bounds__(NTH, 1)
void k_step11() {
    extern __shared__ __align__(1024) unsigned char smraw[];
    const uint32_t sb = (uint32_t)__cvta_generic_to_shared(smraw);

    const int tid = threadIdx.x;
    const int cta = blockIdx.x;
    const int wid = tid >> 5, lane = tid & 31;
    const int g2 = wid >> 3;            // K-group
    const int wg = wid & 7;             // M-warp within group
    const int rot2 = ((cta >> 4) & 3) * 2;   // rotated start chunk (kc=64 units)

    // ---- resident W (fp16, 32x1024) -> SMEM SW128 blocked-atom ----
    {
        const __half* wsrc = g_Whp + (long)cta * 32 * HDIM;
        unsigned char* wdst = smraw + SM_W;
        for (int idx = tid; idx < 32 * 128; idx += NTH) {
            int r = idx >> 7, cc = idx & 127;
            int c0 = cc * 8;
            uint32_t byte = (uint32_t)(((r >> 3) + (c0 >> 6) * 4) * 1024 + (r & 7) * 128 + (c0 & 63) * 2);
            *(uint4*)(wdst + SWZ128(byte)) = *(const uint4*)(wsrc + r * HDIM + c0);
        }
    }

    // ---- ldmatrix lane addresses ----
    const int aq = lane >> 3, al = lane & 7;
    const int am = wg * 16 + ((aq & 1) ? 8 : 0) + al;
    const uint32_t akb = (uint32_t)((aq >> 1) * 16);
    const uint32_t aR  = (uint32_t)((am >> 3) * 1024 + (am & 7) * 128);
    const uint32_t aC  = (uint32_t)((am & 7) * 16);
    const int bq = lane >> 3, bl = lane & 7;
    const int bn_off = (bq >> 1) * 8;
    const uint32_t bkb = (uint32_t)((bq & 1) * 16);
    uint32_t bR[2], bC[2];
#pragma unroll
    for (int p = 0; p < 2; p++) {
        int n = p * 16 + bn_off + bl;
        bR[p] = (uint32_t)((n >> 3) * 1024 + (n & 7) * 128);
        bC[p] = (uint32_t)((n & 7) * 16);
    }

    // ---- coalesced loader mapping (kc=64: 4 cpa16 per thread per chunk) ----
    const int seg  = tid & 7;
    const int slot = (tid >> 3) & 31;
    const uint32_t dst0 = (uint32_t)((slot >> 3) * 1024 + (slot & 7) * 128 + seg * 16);
    const uint32_t abase = sb + SM_A + (uint32_t)g2 * 65536;   // 4 bufs x 16KB
    const int barid = 1 + g2;
    const int coh0 = g2 * 4;            // this group's first cohort (k-block)

    // epilogue mapping (group 0)
    const int er = lane >> 2, ec = (lane & 3) * 2;
    const int b0 = wg * 16 + er;
    const int ridx = wg * 32 + lane;
    float* sR = (float*)(smraw + SM_R);

    float creg[2][2];
    creg[0][0] = creg[0][1] = creg[1][0] = creg[1][1] = 0.f;

    __syncthreads();

    for (int t = 0; t < SLEN; t++) {
        const int par = t & 1, nxt = par ^ 1;
        const unsigned tgt = 16u * (unsigned)t;
        const __half* srcH = g_h16[par] + (long)slot * HDIM + g2 * 512 + seg * 8;

        // gates preload first (independent of flags; overlaps skew wait)
        float2 gv[4][2];
        if (g2 == 0) {
            const float* gx = g_gatesx + ((long)(t * 128 + cta) * 4) * 1024;
#pragma unroll
            for (int g = 0; g < 4; g++) {
                gv[g][0] = *(const float2*)(gx + (g * 128 + b0) * 8 + ec);
                gv[g][1] = *(const float2*)(gx + (g * 128 + b0 + 8) * 8 + ec);
            }
        }

        // prologue: chunks 0,1 (rotated) into bufs 0,1
#pragma unroll
        for (int c = 0; c < 2; c++) {
            const int lb = (rot2 + c) & 7;
            waitflag(coh0 + (lb >> 1), tgt);
            uint32_t dst = abase + (uint32_t)c * 16384;
            const __half* sH = srcH + lb * 64;
#pragma unroll
            for (int i = 0; i < 4; i++)
                cpa16(dst + SWZ128(dst0 + i * 4096), sH + i * 32 * HDIM);
            CP_COMMIT();
        }

        float acc[4][4];
#pragma unroll
        for (int nt = 0; nt < 4; nt++)
#pragma unroll
            for (int q = 0; q < 4; q++) acc[nt][q] = 0.f;

        for (int s = 0; s < 8; s++) {
            const int lb = (rot2 + s) & 7;
            cp_wait<1>();
            BARG(barid);   // chunk s arrived; all warps done reading chunk s-1

            // issue chunk s+2 into buf (s+2)&3 (free: held chunk s-2... for
            // s=0,1 bufs 2,3 are empty; for s>=2 buf held chunk s-2, fully
            // read before the BARG at top of iteration s-1? -> held chunk
            // (s+2)-4 = s-2, whose reads finished before BARG of s-1; this
            // BARG (top of s) certainly covers it.)
            if (s + 2 < 8) {
                const int lb2 = (rot2 + s + 2) & 7;
                waitflag(coh0 + (lb2 >> 1), tgt);
                uint32_t dst = abase + (uint32_t)((s + 2) & 3) * 16384;
                const __half* sH = srcH + lb2 * 64;
#pragma unroll
                for (int i = 0; i < 4; i++)
                    cpa16(dst + SWZ128(dst0 + i * 4096), sH + i * 32 * HDIM);
            }
            CP_COMMIT();

            const uint32_t aB = abase + (uint32_t)(s & 3) * 16384;
            const uint32_t wB = sb + SM_W + (uint32_t)(g2 * 8 + lb) * 4096;

#pragma unroll
            for (int kt = 0; kt < 4; kt++) {
                const uint32_t ka = (uint32_t)(kt * 32);
                uint32_t ah[4];
                ldsm4(ah[0], ah[1], ah[2], ah[3], aB + aR + ((ka + akb) ^ aC));
#pragma unroll
                for (int p = 0; p < 2; p++) {
                    uint32_t bh[4];
                    ldsm4(bh[0], bh[1], bh[2], bh[3], wB + bR[p] + ((ka + bkb) ^ bC[p]));
#pragma unroll
                    for (int h2 = 0; h2 < 2; h2++) {
                        float* d = acc[p * 2 + h2];
                        mma16816(d[0], d[1], d[2], d[3], ah[0], ah[1], ah[2], ah[3], bh[h2 * 2], bh[h2 * 2 + 1]);
                    }
                }
            }
        }

        // reduce: group 1 -> SMEM
        if (g2 == 1) {
#pragma unroll
            for (int q = 0; q < 16; q++)
                sR[q * 256 + ridx] = acc[q >> 2][q & 3];
        }
        __syncthreads();

        if (g2 == 0) {
#pragma unroll
            for (int q = 0; q < 16; q++)
                acc[q >> 2][q & 3] += sR[q * 256 + ridx];

            // register-local cell update: rows b0, b0+8; cols cta*8+ec+{0,1}
#pragma unroll
            for (int h2 = 0; h2 < 2; h2++) {
                const int bb = b0 + h2 * 8;
                float hn[2];
                __half hh[2];
#pragma unroll
                for (int q = 0; q < 2; q++) {
                    float pi = acc[0][h2 * 2 + q] + (q ? gv[0][h2].y : gv[0][h2].x);
                    float pf = acc[1][h2 * 2 + q] + (q ? gv[1][h2].y : gv[1][h2].x);
                    float pg = acc[2][h2 * 2 + q] + (q ? gv[2][h2].y : gv[2][h2].x);
                    float po = acc[3][h2 * 2 + q] + (q ? gv[3][h2].y : gv[3][h2].x);
                    float iv = fsigmoid(pi);
                    float fv = fsigmoid(pf);
                    float gg = ftanh(pg);
                    float ov = fsigmoid(po);
                    float cn = fv * creg[h2][q] + iv * gg;
                    creg[h2][q] = cn;
                    hn[q] = ov * ftanh(cn);
                    hh[q] = __float2half_rn(hn[q]);
                }
                long hb = (long)bb * HDIM + cta * 8 + ec;
                *(__half2*)&g_h16[nxt][hb] = *(__half2*)hh;
                if (t == SLEN - 1) *(float2*)&g_h[hb] = make_float2(hn[0], hn[1]);
            }
        }

        // release this CTA's cohort (h[t+1] columns published)
        __syncthreads();
        if (tid == 0) {
            __threadfence();
            atomicAdd(&g_flag[(cta >> 4) * 32], 1u);
        }
    }
}

// ---------------------------------------------------------------------------
__global__ void k_fc(const float* __restrict__ fcW, const float* __restrict__ fcb,
                     float* __restrict__ out) {
    int b = blockIdx.x;
    int w = threadIdx.x >> 5, lane = threadIdx.x & 31;
    if (w >= ODIM) return;
    const float* hrow = g_h + b * HDIM;
    const float* wrow = fcW + w * HDIM;
    float s = 0.f;
    for (int k = lane; k < HDIM; k += 32) s += hrow[k] * wrow[k];
#pragma unroll
    for (int off = 16; off; off >>= 1) s += __shfl_xor_sync(0xffffffffu, s, off);
    if (lane == 0) out[b * ODIM + w] = s + fcb[w];
}

// ---------------------------------------------------------------------------
extern "C" void kernel_launch(void* const* d_in, const int* in_sizes, int n_in,
                              void* d_out, int out_size) {
    const void*  x   = d_in[0];
    const float* emb = (const float*)d_in[1];
    const float* Wii = (const float*)d_in[2];
    const float* bii = (const float*)d_in[3];
    const float* Whi = (const float*)d_in[4];
    const float* Wif = (const float*)d_in[5];
    const float* bif = (const float*)d_in[6];
    const float* Whf = (const float*)d_in[7];
    const float* Wig = (const float*)d_in[8];
    const float* big = (const float*)d_in[9];
    const float* Whg = (const float*)d_in[10];
    const float* Wio = (const float*)d_in[11];
    const float* bio = (const float*)d_in[12];
    const float* Who = (const float*)d_in[13];
    const float* fcW = (const float*)d_in[14];
    const float* fcb = (const float*)d_in[15];
    float* out = (float*)d_out;

    cudaFuncSetAttribute(k_step11, cudaFuncAttributeMaxDynamicSharedMemorySize,
                         SMEM_TC11);

    k_prep<<<2048, 256>>>(x, emb, Wii, Wif, Wig, Wio, Whi, Whf, Whg, Who);
    k_igemm_tc<<<dim3(NG / 128, MTOT / 128), 256>>>(bii, bif, big, bio);
    k_step11<<<NCTA, NTH, SMEM_TC11>>>();
    k_fc<<<BD, 320>>>(fcW, fcb, out);
}

// round 17
// speedup vs baseline: 1.0876x; 1.0876x over previous
#include <cuda_runtime.h>
#include <cuda_fp16.h>
#include <math.h>
#include <stdint.h>

// Problem dims
#define BD    128
#define SLEN  256
#define EDIM  512
#define HDIM  1024
#define ODIM  10
#define NG    4096
#define MTOT  (BD*SLEN)

#define NCTA  128
#define NTH   512     // 16 warps: 2 K-groups x 8 M-warps

// ---------------------------------------------------------------------------
// Device scratch
// ---------------------------------------------------------------------------
// gatesx layout: [s][hb(128)][g(4)][b(128)][8]
__device__ float g_gatesx[(long)SLEN * BD * NG];
__device__ float g_h[BD * HDIM];

__device__ __half g_h16[2][BD * HDIM];      // fp16 h, ping-pong
__device__ __half g_Whp[(long)NG * HDIM];   // fp16 W, n = cta*32 + g*8 + j
__device__ __half g_Wip[(long)NG * EDIM];   // fp16 W, n = g*1024 + col
__device__ __half g_e16[(long)MTOT * EDIM]; // fp16 gathered embeddings

// per-cohort dataflow flags: cohort c = producers of h cols [128c, 128c+128)
__device__ unsigned g_flag[8 * 32];

// ---------------------------------------------------------------------------
__device__ __forceinline__ void mma16816(float& d0, float& d1, float& d2, float& d3,
                                         uint32_t a0, uint32_t a1, uint32_t a2, uint32_t a3,
                                         uint32_t b0, uint32_t b1) {
    asm volatile("mma.sync.aligned.m16n8k16.row.col.f32.f16.f16.f32 "
                 "{%0,%1,%2,%3}, {%4,%5,%6,%7}, {%8,%9}, {%0,%1,%2,%3};"
                 : "+f"(d0), "+f"(d1), "+f"(d2), "+f"(d3)
                 : "r"(a0), "r"(a1), "r"(a2), "r"(a3), "r"(b0), "r"(b1));
}

__device__ __forceinline__ void ldsm4(uint32_t& r0, uint32_t& r1, uint32_t& r2,
                                      uint32_t& r3, uint32_t addr) {
    asm volatile("ldmatrix.sync.aligned.m8n8.x4.shared.b16 {%0,%1,%2,%3}, [%4];"
                 : "=r"(r0), "=r"(r1), "=r"(r2), "=r"(r3) : "r"(addr));
}

__device__ __forceinline__ void cpa16(uint32_t s, const void* g) {
    asm volatile("cp.async.cg.shared.global [%0], [%1], 16;\n" :: "r"(s), "l"(g));
}
#define CP_COMMIT() asm volatile("cp.async.commit_group;\n" ::: "memory")
template <int N> __device__ __forceinline__ void cp_wait() {
    asm volatile("cp.async.wait_group %0;\n" :: "n"(N) : "memory");
}
#define BARG(id) asm volatile("bar.sync %0, 256;" :: "r"(id) : "memory")

#define SWZ128(x) ((x) ^ (((x) >> 3) & 0x70))

// fast activations
__device__ __forceinline__ float fsigmoid(float x) {
    return __fdividef(1.f, 1.f + __expf(-x));
}
__device__ __forceinline__ float ftanh(float x) {
    return 1.f - __fdividef(2.f, __expf(2.f * x) + 1.f);
}

// wait until cohort c's flag reaches target (lane0 acquire-poll + warp sync)
__device__ __forceinline__ void waitflag(int c, unsigned target) {
    if ((threadIdx.x & 31) == 0) {
        unsigned v;
        do {
            asm volatile("ld.acquire.gpu.u32 %0, [%1];"
                         : "=r"(v) : "l"(g_flag + c * 32) : "memory");
        } while (v < target);
    }
    __syncwarp();
}

// ---------------------------------------------------------------------------
// Merged prep (grid-stride): embedding gather+fp16, W packs, h/flag init.
// ---------------------------------------------------------------------------
__global__ void k_prep(const void* __restrict__ xv, const float* __restrict__ emb,
                       const float* __restrict__ Wii, const float* __restrict__ Wif,
                       const float* __restrict__ Wig, const float* __restrict__ Wio,
                       const float* __restrict__ Whi, const float* __restrict__ Whf,
                       const float* __restrict__ Whg, const float* __restrict__ Who) {
    const int nb = gridDim.x, blk = blockIdx.x, tid = threadIdx.x;

    __shared__ int s64;
    if (tid == 0) {
        const int* xw = (const int*)xv;
        int zeros = 0;
        for (int i = 0; i < 64; i++)
            if (xw[2 * i + 1] == 0) zeros++;
        s64 = (zeros >= 60) ? 1 : 0;
    }
    __syncthreads();

    for (int m = blk; m < MTOT; m += nb) {
        long tok = s64 ? (long)((const long long*)xv)[m] : (long)((const int*)xv)[m];
        const float* src = emb + tok * EDIM;
        for (int k = tid; k < EDIM; k += 256)
            g_e16[(long)m * EDIM + k] = __float2half_rn(src[k]);
    }
    for (int n = blk; n < NG; n += nb) {
        int g = n >> 10, col = n & 1023;
        const float* src = ((g == 0) ? Wii : (g == 1) ? Wif : (g == 2) ? Wig : Wio)
                           + (long)col * EDIM;
        for (int k = tid; k < EDIM; k += 256)
            g_Wip[(long)n * EDIM + k] = __float2half_rn(src[k]);
    }
    for (int n = blk; n < NG; n += nb) {
        int hb = n >> 5, r = n & 31, g = r >> 3, j = r & 7;
        int h = hb * 8 + j;
        const float* src = ((g == 0) ? Whi : (g == 1) ? Whf : (g == 2) ? Whg : Who)
                           + (long)h * HDIM;
        for (int k = tid; k < HDIM; k += 256)
            g_Whp[(long)n * HDIM + k] = __float2half_rn(src[k]);
    }
    for (int i = blk * 256 + tid; i < BD * HDIM; i += nb * 256)
        g_h16[0][i] = __float2half(0.f);
    for (int i = blk * 256 + tid; i < 8 * 32; i += nb * 256)
        g_flag[i] = 0u;
}

// ---------------------------------------------------------------------------
// Input projection GEMM: [32768 x 512] @ [512 x 4096], fp16 single-term.
// ---------------------------------------------------------------------------
#define IP 24
__global__ __launch_bounds__(256)
void k_igemm_tc(const float* __restrict__ bi, const float* __restrict__ bf2,
                const float* __restrict__ bg, const float* __restrict__ bo) {
    __shared__ __align__(16) __half sm[2][2][128 * IP];

    const int tid = threadIdx.x;
    const int n0 = blockIdx.x * 128;
    const int M0 = blockIdx.y * 128;

    const int w = tid >> 5, lane = tid & 31;
    const int g = lane >> 2, tig = lane & 3;
    const int m0w = (w >> 1) * 32, n0w = (w & 1) * 64;

    const int sel0 = tid >> 7, idx0 = tid & 127;
    const __half* gp0 = sel0 ? (g_Wip + (long)(n0 + idx0) * EDIM)
                             : (g_e16 + (long)(M0 + idx0) * EDIM);

    float acc[2][8][4];
#pragma unroll
    for (int mt = 0; mt < 2; mt++)
#pragma unroll
        for (int nt = 0; nt < 8; nt++)
#pragma unroll
            for (int q = 0; q < 4; q++) acc[mt][nt][q] = 0.f;

    uint4 p0[2];
    p0[0] = ((const uint4*)gp0)[0]; p0[1] = ((const uint4*)gp0)[1];
    {
        uint4* d = (uint4*)(&sm[0][sel0][idx0 * IP]);
        d[0] = p0[0]; d[1] = p0[1];
    }
    __syncthreads();

    const int NSTAGE = EDIM / 16;
    for (int s = 0; s < NSTAGE; s++) {
        int buf = s & 1;
        bool more = (s + 1 < NSTAGE);
        if (more) {
            gp0 += 16;
            p0[0] = ((const uint4*)gp0)[0]; p0[1] = ((const uint4*)gp0)[1];
        }
        const __half* Am = sm[buf][0];
        const __half* Bm = sm[buf][1];
        const int kb = 2 * tig;

        uint32_t aF[2][4], bF[8][2];
#pragma unroll
        for (int mt = 0; mt < 2; mt++) {
            int rw = (m0w + mt * 16 + g) * IP + kb;
            aF[mt][0] = *(const uint32_t*)(Am + rw);
            aF[mt][1] = *(const uint32_t*)(Am + rw + 8 * IP);
            aF[mt][2] = *(const uint32_t*)(Am + rw + 8);
            aF[mt][3] = *(const uint32_t*)(Am + rw + 8 * IP + 8);
        }
#pragma unroll
        for (int nt = 0; nt < 8; nt++) {
            int cw = (n0w + nt * 8 + g) * IP + kb;
            bF[nt][0] = *(const uint32_t*)(Bm + cw);
            bF[nt][1] = *(const uint32_t*)(Bm + cw + 8);
        }
#pragma unroll
        for (int mt = 0; mt < 2; mt++)
#pragma unroll
            for (int nt = 0; nt < 8; nt++) {
                float* d = acc[mt][nt];
                mma16816(d[0], d[1], d[2], d[3], aF[mt][0], aF[mt][1], aF[mt][2], aF[mt][3], bF[nt][0], bF[nt][1]);
            }

        if (more) {
            uint4* d = (uint4*)(&sm[buf ^ 1][sel0][idx0 * IP]);
            d[0] = p0[0]; d[1] = p0[1];
        }
        __syncthreads();
    }

#pragma unroll
    for (int mt = 0; mt < 2; mt++) {
        int r0 = m0w + mt * 16 + g;
#pragma unroll
        for (int nt = 0; nt < 8; nt++) {
            int col  = n0w + nt * 8 + 2 * tig;
            int ncol = n0 + col;
            int gate = ncol >> 10, hcol = ncol & 1023;
            int hb = hcol >> 3, j = hcol & 7;
            const float* bptr = (gate == 0) ? bi : (gate == 1) ? bf2 : (gate == 2) ? bg : bo;
            float bv0 = bptr[hcol], bv1 = bptr[hcol + 1];
#pragma unroll
            for (int hf = 0; hf < 2; hf++) {
                int mrow = M0 + r0 + hf * 8;
                int b = mrow >> 8, ss = mrow & 255;
                float2 v = make_float2(acc[mt][nt][hf * 2] + bv0, acc[mt][nt][hf * 2 + 1] + bv1);
                long off = ((((long)ss * 128 + hb) * 4 + gate) * 128 + b) * 8 + j;
                *(float2*)(g_gatesx + off) = v;
            }
        }
    }
}

// ---------------------------------------------------------------------------
// Persistent LSTM step kernel v12: R15 base (kc=128, 2-buf, cohort flags +
// rotation) + SPLIT EPILOGUE: g0 warps 0-3 finalize rows 0-63, g1 warps 4-7
// finalize rows 64-127 (bit-identical math; halves boundary latency).
// ---------------------------------------------------------------------------
#define SM_A   0                       // 2 groups x 2 bufs x 32KB = 128KB
#define SM_W   131072                  // 64KB resident W
#define SM_R   (131072 + 65536)        // 16KB reduce
#define SMEM_TC12 (SM_R + 16384)       // 212992

__global__ __launch_bounds__(NTH, 1)
void k_step12() {
    extern __shared__ __align__(1024) unsigned char smraw[];
    const uint32_t sb = (uint32_t)__cvta_generic_to_shared(smraw);

    const int tid = threadIdx.x;
    const int cta = blockIdx.x;
    const int wid = tid >> 5, lane = tid & 31;
    const int g2 = wid >> 3;            // K-group
    const int wg = wid & 7;             // M-warp within group
    const int rot = (cta >> 4) & 3;     // rotation: own cohort's local block
    const bool fin = (g2 == 0) ? (wg < 4) : (wg >= 4);   // finalizer warp?

    // ---- resident W (fp16, 32x1024) -> SMEM SW128 blocked-atom ----
    {
        const __half* wsrc = g_Whp + (long)cta * 32 * HDIM;
        unsigned char* wdst = smraw + SM_W;
        for (int idx = tid; idx < 32 * 128; idx += NTH) {
            int r = idx >> 7, cc = idx & 127;
            int c0 = cc * 8;
            uint32_t byte = (uint32_t)(((r >> 3) + (c0 >> 6) * 4) * 1024 + (r & 7) * 128 + (c0 & 63) * 2);
            *(uint4*)(wdst + SWZ128(byte)) = *(const uint4*)(wsrc + r * HDIM + c0);
        }
    }

    // ---- ldmatrix lane addresses ----
    const int aq = lane >> 3, al = lane & 7;
    const int am = wg * 16 + ((aq & 1) ? 8 : 0) + al;
    const uint32_t akb = (uint32_t)((aq >> 1) * 16);
    const uint32_t aR  = (uint32_t)((am >> 3) * 1024 + (am & 7) * 128);
    const uint32_t aC  = (uint32_t)((am & 7) * 16);
    const int bq = lane >> 3, bl = lane & 7;
    const int bn_off = (bq >> 1) * 8;
    const uint32_t bkb = (uint32_t)((bq & 1) * 16);
    uint32_t bR[2], bC[2];
#pragma unroll
    for (int p = 0; p < 2; p++) {
        int n = p * 16 + bn_off + bl;
        bR[p] = (uint32_t)((n >> 3) * 1024 + (n & 7) * 128);
        bC[p] = (uint32_t)((n & 7) * 16);
    }

    // ---- coalesced loader mapping ----
    const int seg  = tid & 7;
    const int slot = (tid >> 3) & 31;
    const uint32_t dst0 = (uint32_t)((slot >> 3) * 1024 + (slot & 7) * 128 + seg * 16);
    const uint32_t abase = sb + SM_A + (uint32_t)g2 * 65536;   // 2 bufs x 32KB
    const int barid = 1 + g2;
    const int coh0 = g2 * 4;            // this group's first cohort (k-block)

    // epilogue mapping
    const int er = lane >> 2, ec = (lane & 3) * 2;
    const int b0 = wg * 16 + er;
    const int ridx = wg * 32 + lane;    // slots 0-127 for wg0-3, 128-255 for wg4-7
    float* sR = (float*)(smraw + SM_R);

    float creg[2][2];
    creg[0][0] = creg[0][1] = creg[1][0] = creg[1][1] = 0.f;

    __syncthreads();

    for (int t = 0; t < SLEN; t++) {
        const int par = t & 1, nxt = par ^ 1;
        const unsigned tgt = 16u * (unsigned)t;
        const __half* srcH = g_h16[par] + (long)slot * HDIM + g2 * 512 + seg * 8;

        // gates preload (finalizing warps only; overlaps skew wait)
        float2 gv[4][2];
        if (fin) {
            const float* gx = g_gatesx + ((long)(t * 128 + cta) * 4) * 1024;
#pragma unroll
            for (int g = 0; g < 4; g++) {
                gv[g][0] = *(const float2*)(gx + (g * 128 + b0) * 8 + ec);
                gv[g][1] = *(const float2*)(gx + (g * 128 + b0 + 8) * 8 + ec);
            }
        }

        // prologue: rotated chunks s=0,1 into bufs 0,1, gated per cohort
#pragma unroll
        for (int c = 0; c < 2; c++) {
            const int lb = (rot + c) & 3;
            waitflag(coh0 + lb, tgt);
            uint32_t dst = abase + (uint32_t)c * 32768;
            const __half* sH = srcH + lb * 128;
#pragma unroll
            for (int hf = 0; hf < 2; hf++)
#pragma unroll
                for (int i = 0; i < 4; i++)
                    cpa16(dst + (uint32_t)hf * 16384 + SWZ128(dst0 + i * 4096),
                          sH + hf * 64 + i * 32 * HDIM);
            CP_COMMIT();
        }

        float acc[4][4];
#pragma unroll
        for (int nt = 0; nt < 4; nt++)
#pragma unroll
            for (int q = 0; q < 4; q++) acc[nt][q] = 0.f;

        for (int s = 0; s < 4; s++) {
            const int lb = (rot + s) & 3;
            cp_wait<1>();
            BARG(barid);                       // chunk s visible group-wide

            const uint32_t aB = abase + (uint32_t)(s & 1) * 32768;
            const uint32_t wB = sb + SM_W + (uint32_t)(g2 * 8 + lb * 2) * 4096;

#pragma unroll
            for (int kt = 0; kt < 8; kt++) {
                const uint32_t hf = (uint32_t)(kt >> 2);
                const uint32_t ka = (uint32_t)((kt & 3) * 32);
                uint32_t ah[4];
                ldsm4(ah[0], ah[1], ah[2], ah[3],
                      aB + hf * 16384 + aR + ((ka + akb) ^ aC));
#pragma unroll
                for (int p = 0; p < 2; p++) {
                    uint32_t bh[4];
                    ldsm4(bh[0], bh[1], bh[2], bh[3],
                          wB + hf * 4096 + bR[p] + ((ka + bkb) ^ bC[p]));
#pragma unroll
                    for (int h2 = 0; h2 < 2; h2++) {
                        float* d = acc[p * 2 + h2];
                        mma16816(d[0], d[1], d[2], d[3], ah[0], ah[1], ah[2], ah[3], bh[h2 * 2], bh[h2 * 2 + 1]);
                    }
                }
            }

            BARG(barid);                       // all reads of buf (s&1) done
            if (s + 2 < 4) {
                const int lb2 = (rot + s + 2) & 3;
                waitflag(coh0 + lb2, tgt);
                uint32_t dst = abase + (uint32_t)(s & 1) * 32768;
                const __half* sH = srcH + lb2 * 128;
#pragma unroll
                for (int hf = 0; hf < 2; hf++)
#pragma unroll
                    for (int i = 0; i < 4; i++)
                        cpa16(dst + (uint32_t)hf * 16384 + SWZ128(dst0 + i * 4096),
                              sH + hf * 64 + i * 32 * HDIM);
            }
            CP_COMMIT();
        }

        // exchange: non-finalizing warps write partials (disjoint slot ranges)
        if (!fin) {
#pragma unroll
            for (int q = 0; q < 16; q++)
                sR[q * 256 + ridx] = acc[q >> 2][q & 3];
        }
        __syncthreads();

        if (fin) {
#pragma unroll
            for (int q = 0; q < 16; q++)
                acc[q >> 2][q & 3] += sR[q * 256 + ridx];

            // register-local cell update: rows b0, b0+8; cols cta*8+ec+{0,1}
#pragma unroll
            for (int h2 = 0; h2 < 2; h2++) {
                const int bb = b0 + h2 * 8;
                float hn[2];
                __half hh[2];
#pragma unroll
                for (int q = 0; q < 2; q++) {
                    float pi = acc[0][h2 * 2 + q] + (q ? gv[0][h2].y : gv[0][h2].x);
                    float pf = acc[1][h2 * 2 + q] + (q ? gv[1][h2].y : gv[1][h2].x);
                    float pg = acc[2][h2 * 2 + q] + (q ? gv[2][h2].y : gv[2][h2].x);
                    float po = acc[3][h2 * 2 + q] + (q ? gv[3][h2].y : gv[3][h2].x);
                    float iv = fsigmoid(pi);
                    float fv = fsigmoid(pf);
                    float gg = ftanh(pg);
                    float ov = fsigmoid(po);
                    float cn = fv * creg[h2][q] + iv * gg;
                    creg[h2][q] = cn;
                    hn[q] = ov * ftanh(cn);
                    hh[q] = __float2half_rn(hn[q]);
                }
                long hb = (long)bb * HDIM + cta * 8 + ec;
                *(__half2*)&g_h16[nxt][hb] = *(__half2*)hh;
                if (t == SLEN - 1) *(float2*)&g_h[hb] = make_float2(hn[0], hn[1]);
            }
        }

        // release this CTA's cohort (h[t+1] columns published)
        __syncthreads();
        if (tid == 0) {
            __threadfence();
            atomicAdd(&g_flag[(cta >> 4) * 32], 1u);
        }
    }
}

// ---------------------------------------------------------------------------
__global__ void k_fc(const float* __restrict__ fcW, const float* __restrict__ fcb,
                     float* __restrict__ out) {
    int b = blockIdx.x;
    int w = threadIdx.x >> 5, lane = threadIdx.x & 31;
    if (w >= ODIM) return;
    const float* hrow = g_h + b * HDIM;
    const float* wrow = fcW + w * HDIM;
    float s = 0.f;
    for (int k = lane; k < HDIM; k += 32) s += hrow[k] * wrow[k];
#pragma unroll
    for (int off = 16; off; off >>= 1) s += __shfl_xor_sync(0xffffffffu, s, off);
    if (lane == 0) out[b * ODIM + w] = s + fcb[w];
}

// ---------------------------------------------------------------------------
extern "C" void kernel_launch(void* const* d_in, const int* in_sizes, int n_in,
                              void* d_out, int out_size) {
    const void*  x   = d_in[0];
    const float* emb = (const float*)d_in[1];
    const float* Wii = (const float*)d_in[2];
    const float* bii = (const float*)d_in[3];
    const float* Whi = (const float*)d_in[4];
    const float* Wif = (const float*)d_in[5];
    const float* bif = (const float*)d_in[6];
    const float* Whf = (const float*)d_in[7];
    const float* Wig = (const float*)d_in[8];
    const float* big = (const float*)d_in[9];
    const float* Whg = (const float*)d_in[10];
    const float* Wio = (const float*)d_in[11];
    const float* bio = (const float*)d_in[12];
    const float* Who = (const float*)d_in[13];
    const float* fcW = (const float*)d_in[14];
    const float* fcb = (const float*)d_in[15];
    float* out = (float*)d_out;

    cudaFuncSetAttribute(k_step12, cudaFuncAttributeMaxDynamicSharedMemorySize,
                         SMEM_TC12);

    k_prep<<<2048, 256>>>(x, emb, Wii, Wif, Wig, Wio, Whi, Whf, Whg, Who);
    k_igemm_tc<<<dim3(NG / 128, MTOT / 128), 256>>>(bii, bif, big, bio);
    k_step12<<<NCTA, NTH, SMEM_TC12>>>();
    k_fc<<<BD, 320>>>(fcW, fcb, out);
}